// round 1
// baseline (speedup 1.0000x reference)
#include <cuda_runtime.h>
#include <math.h>

#define BB     2
#define NPTS   262144
#define KSLOT  9
#define SDIM   64
#define DDIM   64
#define SCALEF 0.125f

#define TILE    128
#define THREADS 128

// Precomputed per-batch tiny matrices (written by prep_kernel).
__device__ float g_A[BB][KSLOT][DDIM];   // SCALE * (k @ Wq_w)   [9,64]
__device__ float g_V[BB][KSLOT][DDIM];   // slots_full @ out_w^T [9,64]
__device__ float g_c[BB][KSLOT];         // SCALE * (Wq_b . k_j)
__device__ float g_esc[1];               // exp(density_scale)

// ---------------------------------------------------------------------------
// Prep: one block per batch, 576 threads = (j,d) pairs.
// k[j,d]   = Wk_b[d] + sum_s sf[j,s] * Wk_w[d,s]
// A[j,e]   = SCALE * sum_d k[j,d] * Wq_w[d,e]
// V[j,d]   = sum_s sf[j,s] * out_w[d,s]
// c[j]     = SCALE * sum_d Wq_b[d] * k[j,d]
// ---------------------------------------------------------------------------
__global__ void prep_kernel(const float* __restrict__ slots,
                            const float* __restrict__ empty_slot,
                            const float* __restrict__ Wq_w,
                            const float* __restrict__ Wq_b,
                            const float* __restrict__ Wk_w,
                            const float* __restrict__ Wk_b,
                            const float* __restrict__ out_w,
                            const float* __restrict__ density_scale) {
    int b   = blockIdx.x;
    int tid = threadIdx.x;        // 0..575
    int j   = tid >> 6;
    int d   = tid & 63;

    __shared__ float sf[KSLOT][SDIM];
    __shared__ float sk[KSLOT][DDIM];

    sf[j][d] = (j == 0) ? empty_slot[d]
                        : slots[(b * (KSLOT - 1) + (j - 1)) * SDIM + d];
    __syncthreads();

    float kk = Wk_b[d];
    #pragma unroll
    for (int s = 0; s < SDIM; s++)
        kk = fmaf(sf[j][s], Wk_w[d * SDIM + s], kk);
    sk[j][d] = kk;
    __syncthreads();

    float aa = 0.f;
    #pragma unroll
    for (int e = 0; e < DDIM; e++)
        aa = fmaf(sk[j][e], Wq_w[e * DDIM + d], aa);
    g_A[b][j][d] = aa * SCALEF;

    float vv = 0.f;
    #pragma unroll
    for (int s = 0; s < SDIM; s++)
        vv = fmaf(sf[j][s], out_w[d * SDIM + s], vv);
    g_V[b][j][d] = vv;

    if (tid < KSLOT) {
        float cc = 0.f;
        #pragma unroll
        for (int e = 0; e < DDIM; e++)
            cc = fmaf(Wq_b[e], sk[tid][e], cc);
        g_c[b][tid] = cc * SCALEF;
    }
    if (b == 0 && tid == 0) g_esc[0] = expf(density_scale[0]);
}

// ---------------------------------------------------------------------------
// Main: 128 points per 128-thread block.
// ---------------------------------------------------------------------------
__global__ __launch_bounds__(THREADS)
void main_kernel(const float* __restrict__ pf,     // [B,N,64]
                 const float* __restrict__ coor,   // [B,N,3]
                 const float* __restrict__ out_b,  // [64]
                 float* __restrict__ xo_out,       // [B,N,64]
                 float* __restrict__ w_out,        // [B,N,9]
                 float* __restrict__ sig_out) {    // [B,N]

    __shared__ float xs[TILE][68];       // padded: stride 68 -> conflict-free LDS.128
    __shared__ float ws[TILE][12];       // softmax weights, padded to 12
    __shared__ float As[KSLOT * DDIM];
    __shared__ float cs[KSLOT];

    const int tid  = threadIdx.x;
    const int base = blockIdx.x * TILE;          // global point index of tile start
    const int b    = base / NPTS;                // tiles never straddle batches

    // ---- stage x tile (fully coalesced float4 loads) ----
    const float4* pf4 = (const float4*)pf + base * (DDIM / 4);
    #pragma unroll
    for (int i = 0; i < (TILE * 16) / THREADS; i++) {
        int idx = tid + i * THREADS;             // 0..2047
        int p = idx >> 4, ev = idx & 15;
        *(float4*)&xs[p][ev * 4] = pf4[idx];
    }
    // ---- stage A, c ----
    #pragma unroll
    for (int i = tid; i < KSLOT * DDIM; i += THREADS) As[i] = g_A[b][0][i];
    if (tid < KSLOT) cs[tid] = g_c[b][tid];

    // ---- per-thread V columns for the output phase (d-quad q = tid&15) ----
    const int q = tid & 15;
    float4 v[KSLOT];
    #pragma unroll
    for (int j = 0; j < KSLOT; j++)
        v[j] = *(const float4*)&g_V[b][j][q * 4];
    const float4 ob  = *(const float4*)&out_b[q * 4];
    const float  esc = g_esc[0];

    __syncthreads();

    // ---- phase 1: logits / softmax / sigma for my point (p = tid) ----
    float acc[KSLOT];
    #pragma unroll
    for (int j = 0; j < KSLOT; j++) acc[j] = cs[j];

    #pragma unroll
    for (int ev = 0; ev < 16; ev++) {
        float4 x4 = *(const float4*)&xs[tid][ev * 4];
        #pragma unroll
        for (int j = 0; j < KSLOT; j++) {
            float4 a4 = *(const float4*)&As[j * DDIM + ev * 4];
            acc[j] = fmaf(x4.x, a4.x, acc[j]);
            acc[j] = fmaf(x4.y, a4.y, acc[j]);
            acc[j] = fmaf(x4.z, a4.z, acc[j]);
            acc[j] = fmaf(x4.w, a4.w, acc[j]);
        }
    }

    const int g = base + tid;
    float cx = coor[g * 3 + 0];
    float cy = coor[g * 3 + 1];
    float cz = coor[g * 3 + 2];
    bool oob = (fabsf(cx) > 1.0f) || (fabsf(cy) > 1.0f) || (fabsf(cz) > 1.0f);
    if (oob) {
        #pragma unroll
        for (int j = 2; j < KSLOT; j++) acc[j] = -INFINITY;
    }

    float m = acc[0];
    #pragma unroll
    for (int j = 1; j < KSLOT; j++) m = fmaxf(m, acc[j]);
    float ex[KSLOT], sum = 0.f;
    #pragma unroll
    for (int j = 0; j < KSLOT; j++) { ex[j] = __expf(acc[j] - m); sum += ex[j]; }
    const float inv = 1.0f / sum;

    float sig = 0.f;
    #pragma unroll
    for (int j = 1; j < KSLOT; j++)
        sig = fmaf(fmaxf(acc[j], 0.f), ex[j] * inv, sig);
    sig_out[g] = sig * esc;

    #pragma unroll
    for (int j = 0; j < KSLOT; j++) ws[tid][j] = ex[j] * inv;

    __syncthreads();

    // ---- coalesced w write ----
    #pragma unroll
    for (int i = 0; i < (TILE * KSLOT) / THREADS; i++) {   // 9 iters
        int idx = tid + i * THREADS;                       // 0..1151
        int p = idx / KSLOT, jj = idx - p * KSLOT;
        w_out[base * KSLOT + idx] = ws[p][jj];
    }

    // ---- phase 2: xo, 16 threads per point, coalesced float4 stores ----
    const int pg = tid >> 4;                 // 0..7
    #pragma unroll
    for (int it = 0; it < TILE / 8; it++) {
        int p = pg + it * 8;
        float4 w0 = *(const float4*)&ws[p][0];
        float4 w1 = *(const float4*)&ws[p][4];
        float4 w2 = *(const float4*)&ws[p][8];   // only .x (j=8) is valid
        float wv[KSLOT] = {w0.x, w0.y, w0.z, w0.w, w1.x, w1.y, w1.z, w1.w, w2.x};
        float4 o = ob;
        #pragma unroll
        for (int j = 0; j < KSLOT; j++) {
            o.x = fmaf(wv[j], v[j].x, o.x);
            o.y = fmaf(wv[j], v[j].y, o.y);
            o.z = fmaf(wv[j], v[j].z, o.z);
            o.w = fmaf(wv[j], v[j].w, o.w);
        }
        *(float4*)&xo_out[(base + p) * DDIM + q * 4] = o;
    }
}

// ---------------------------------------------------------------------------
extern "C" void kernel_launch(void* const* d_in, const int* in_sizes, int n_in,
                              void* d_out, int out_size) {
    const float* pf    = (const float*)d_in[0];   // point_feats
    // d_in[1] points_emb: unused (identity stand-in in reference)
    const float* slots = (const float*)d_in[2];
    const float* coor  = (const float*)d_in[3];
    const float* empty = (const float*)d_in[4];
    const float* Wq_w  = (const float*)d_in[5];
    const float* Wq_b  = (const float*)d_in[6];
    const float* Wk_w  = (const float*)d_in[7];
    const float* Wk_b  = (const float*)d_in[8];
    const float* out_w = (const float*)d_in[9];
    const float* ob    = (const float*)d_in[10];
    const float* dsc   = (const float*)d_in[11];
    // d_in[12] Nr: unused

    float* out = (float*)d_out;
    float* xo  = out;                                   // [B,N,64]
    float* w   = xo + (size_t)BB * NPTS * DDIM;         // [B,N,9]
    float* sg  = w  + (size_t)BB * NPTS * KSLOT;        // [B,N]

    prep_kernel<<<BB, KSLOT * DDIM>>>(slots, empty, Wq_w, Wq_b, Wk_w, Wk_b,
                                      out_w, dsc);
    main_kernel<<<(BB * NPTS) / TILE, THREADS>>>(pf, coor, ob, xo, w, sg);
}